// round 11
// baseline (speedup 1.0000x reference)
#include <cuda_runtime.h>
#include <cstdint>

// ---------------------------------------------------------------------------
// Fused per-pixel MLP discriminator + BCE mean — INT8 IMMA version, R11.
//   x[4,19,256,512] -> 1x1 convs 19->64->128->256->512->1 (leaky 0.2) -> BCE mean
// disc: CTA = 64 pixels, 512 threads = 4 M-tiles x 4 N-slices, 2 CTAs/SM.
// R11: the 4 N-slice warp-groups are now INDEPENDENT pipelines — each group
//   stages its own quarter of every weight chunk (quarters are contiguous by
//   construction of the packing) and synchronizes with a named barrier
//   (bar.sync 1+wn, 128) instead of CTA-wide __syncthreads per chunk.
//   Full-CTA barriers remain only at requant pass boundaries.
// mma.sync m16n8k32.s8; per-col weight scales + prefix-scan error-feedback
// rounding (R10); per-pixel dynamic activation scales; fp32 epilogues;
// L4+5 fused epilogue.
// ---------------------------------------------------------------------------

#define HW_   (256 * 512)
#define NPIX  (4 * HW_)
#define LEAK  0.2f

#define NCHUNKS    23
#define SLOT_BYTES 8192

__device__ __align__(16) int8_t g_Wpk[174080];
__device__ float g_sw[960];
__device__ double g_acc;

__constant__ int c_gb[23] = {0, 2048, 6144, 10240, 18432, 26624, 34816,
    43008, 51200, 59392, 67584, 75776, 83968, 92160, 100352, 108544, 116736,
    124928, 133120, 141312, 149504, 157696, 165888};
__constant__ int c_sz[23] = {2048, 4096, 4096, 8192, 8192, 8192, 8192,
    8192, 8192, 8192, 8192, 8192, 8192, 8192, 8192, 8192, 8192, 8192, 8192,
    8192, 8192, 8192, 8192};

// One WARP per output column; q_k = rint(cumsum_k) - rint(cumsum_{k-1}).
__global__ void prep_kernel(const float* __restrict__ W1, const float* __restrict__ W2,
                            const float* __restrict__ W3, const float* __restrict__ W4) {
    const int lane = threadIdx.x & 31;
    const int col = blockIdx.x * 8 + (threadIdx.x >> 5);
    if (col == 0 && lane == 0) g_acc = 0.0;
    if (col >= 960) return;

    const float* Wrow; int K, nc, layer;
    if (col < 64)       { layer = 0; nc = col;       K = 19;  Wrow = W1 + nc * 19;  }
    else if (col < 192) { layer = 1; nc = col - 64;  K = 64;  Wrow = W2 + nc * 64;  }
    else if (col < 448) { layer = 2; nc = col - 192; K = 128; Wrow = W3 + nc * 128; }
    else                { layer = 3; nc = col - 448; K = 256; Wrow = W4 + nc * 256; }

    float v[8]; float m = 0.f;
#pragma unroll
    for (int j = 0; j < 8; ++j) {
        const int k = lane * 8 + j;
        v[j] = (k < K) ? Wrow[k] : 0.f;
        m = fmaxf(m, fabsf(v[j]));
    }
#pragma unroll
    for (int o = 16; o > 0; o >>= 1) m = fmaxf(m, __shfl_xor_sync(0xffffffffu, m, o));
    const float qsc = (m > 0.f) ? 127.f / m : 0.f;

    float p[8]; float s = 0.f;
#pragma unroll
    for (int j = 0; j < 8; ++j) { s += v[j] * qsc; p[j] = s; }

    float inc = s;
#pragma unroll
    for (int o = 1; o < 32; o <<= 1) {
        const float t = __shfl_up_sync(0xffffffffu, inc, o);
        if (lane >= o) inc += t;
    }
    const float base = inc - s;

    float Rprev = rintf(base);
    const int Kp = (layer == 0) ? 32 : K;
#pragma unroll
    for (int j = 0; j < 8; ++j) {
        const int k = lane * 8 + j;
        if (k >= Kp) break;
        const float R = rintf(base + p[j]);
        float q = R - Rprev;
        Rprev = R;
        q = fminf(127.f, fmaxf(-127.f, q));
        const int8_t qb = (k < K) ? (int8_t)(int)q : (int8_t)0;

        int bse, ncl = nc;
        if (layer == 0)      bse = 0;
        else if (layer == 1) bse = 2048  + (k >> 5) * 4096;
        else if (layer == 2) bse = 10240 + (k >> 5) * 8192;
        else { bse = 43008 + ((nc >> 8) * 8 + (k >> 5)) * 8192; ncl = nc & 255; }
        const int kl = k & 31, tq = (kl >> 2) & 3, hi = kl >> 4, jj = kl & 3;
        g_Wpk[bse + (ncl * 4 + tq) * 8 + hi * 4 + jj] = qb;
    }
    if (lane == 0) g_sw[col] = (m > 0.f) ? m * (1.f / 127.f) : 0.f;
}

__device__ __forceinline__ float leaky(float v) { return fmaxf(v, LEAK * v); }

__device__ __forceinline__ void imma(int* c, const uint32_t* a, uint32_t b0, uint32_t b1) {
    asm volatile(
        "mma.sync.aligned.m16n8k32.row.col.s32.s8.s8.s32 "
        "{%0,%1,%2,%3},{%4,%5,%6,%7},{%8,%9},{%0,%1,%2,%3};\n"
        : "+r"(c[0]), "+r"(c[1]), "+r"(c[2]), "+r"(c[3])
        : "r"(a[0]), "r"(a[1]), "r"(a[2]), "r"(a[3]), "r"(b0), "r"(b1));
}

__device__ __forceinline__ void cp_async16(void* dst, const void* src) {
    const uint32_t d = (uint32_t)__cvta_generic_to_shared(dst);
    asm volatile("cp.async.cg.shared.global [%0], [%1], 16;\n" :: "r"(d), "l"(src) : "memory");
}
__device__ __forceinline__ void cp_commit() {
    asm volatile("cp.async.commit_group;\n" ::: "memory");
}
template <int N> __device__ __forceinline__ void cp_wait() {
    asm volatile("cp.async.wait_group %0;\n" :: "n"(N) : "memory");
}
__device__ __forceinline__ void barn(int id, int cnt) {
    asm volatile("bar.sync %0, %1;" :: "r"(id), "r"(cnt) : "memory");
}

// Stage ONLY group wn's quarter of chunk c (quarters are contiguous in the
// packed layout for every layer). Always commits a (possibly empty) group.
__device__ __forceinline__ void stage_grp(int c, char* ring, int wn, int gtid) {
    if (c < NCHUNKS) {
        const int qsz = c_sz[c] >> 2;
        char* dst = ring + (c & 3) * SLOT_BYTES + wn * qsz;
        const char* src = (const char*)g_Wpk + c_gb[c] + wn * qsz;
        for (int off = gtid * 16; off < qsz; off += 128 * 16)
            cp_async16(dst + off, src + off);
    }
    cp_commit();
}

// SMEM offsets (bytes), M=64. Strides 48/80/144/272: 16B-aligned, conflict-free.
#define SO_XS    0
#define SO_H1    3072
#define SO_H2    8192
#define SO_H3    17408
#define SO_RING  34816
#define SO_BIAS  67584
#define SO_W5    71424
#define SO_SW    73472
#define SO_DS0   77312
#define SO_DS1   77568
#define SO_QS    77824
#define SO_RMAX  78080
#define SO_ZS    78336
#define SO_RED   78592
#define SMEM_BYTES 78656

// One GEMM pass, M=64. Mainloop syncs are per-group named barriers; the
// requant epilogue (non-FUSE) uses full-CTA barriers and ends with one so h
// stores are visible to every group's next-pass ldmatrix.
template <int KP, int NW, int SS, int DS, bool FUSE>
__device__ __forceinline__ void run_pass(
    const int8_t* sA, int8_t* sD, char* ring,
    const float* __restrict__ bias, const float* __restrict__ swc,
    const float* saIn, float* dsOut, float* sqs, unsigned* rmax,
    const float* w5, float* zacc,
    int ncol0, int chunk_col0, int& chunk, int wm, int wn, int lane, int tid)
{
    constexpr int N8 = NW / 8;
    const int g = lane >> 2, tq = lane & 3;
    const int gtid = wm * 32 + lane;

    int acc[N8][4];
#pragma unroll
    for (int n = 0; n < N8; ++n)
#pragma unroll
        for (int q = 0; q < 4; ++q) acc[n][q] = 0;

    const uint32_t abase = (uint32_t)__cvta_generic_to_shared(
        sA + (wm * 16 + (lane & 15)) * SS) + ((lane >> 4) << 4);
    const int wbase = (ncol0 - chunk_col0) * 4 + tq;

#pragma unroll 1
    for (int cc = 0; cc < KP / 32; ++cc) {
        cp_wait<2>();
        barn(1 + wn, 128);                 // group-local: 4 warps of this wn
        stage_grp(chunk + 3, ring, wn, gtid);
        const char* slot = ring + (chunk & 3) * SLOT_BYTES;

        uint32_t a[4];
        asm volatile("ldmatrix.sync.aligned.m8n8.x4.shared.b16 {%0,%1,%2,%3},[%4];\n"
            : "=r"(a[0]), "=r"(a[1]), "=r"(a[2]), "=r"(a[3])
            : "r"(abase + cc * 32));

#pragma unroll
        for (int n8 = 0; n8 < N8; ++n8) {
            const uint2 wv = *(const uint2*)(slot + ((wbase + (n8 * 8 + g) * 4) << 3));
            imma(acc[n8], a, wv.x, wv.y);
        }
        ++chunk;
    }

    // ---- epilogue: rows r0 (acc[.][0..1]) and r0+8 (acc[.][2..3]) ----
    const int r0 = wm * 16 + g;
    const float sa0 = saIn[r0], sa1 = saIn[r0 + 8];
    float lm0 = 0.f, lm1 = 0.f;

#pragma unroll
    for (int n8 = 0; n8 < N8; ++n8) {
        const int c0 = ncol0 + n8 * 8 + tq * 2;
        const float sw0 = swc[c0], sw1 = swc[c0 + 1];
        const float bb0 = bias[c0], bb1 = bias[c0 + 1];
        const float v0 = leaky(fmaf((float)acc[n8][0], sa0 * sw0, bb0));
        const float v1 = leaky(fmaf((float)acc[n8][1], sa0 * sw1, bb1));
        const float v2 = leaky(fmaf((float)acc[n8][2], sa1 * sw0, bb0));
        const float v3 = leaky(fmaf((float)acc[n8][3], sa1 * sw1, bb1));
        if (FUSE) {
            const float w50 = w5[c0], w51 = w5[c0 + 1];
            zacc[0] += v0 * w50 + v1 * w51;
            zacc[1] += v2 * w50 + v3 * w51;
        } else {
            lm0 = fmaxf(lm0, fmaxf(fabsf(v0), fabsf(v1)));
            lm1 = fmaxf(lm1, fmaxf(fabsf(v2), fabsf(v3)));
            acc[n8][0] = __float_as_int(v0); acc[n8][1] = __float_as_int(v1);
            acc[n8][2] = __float_as_int(v2); acc[n8][3] = __float_as_int(v3);
        }
    }

    if (!FUSE) {
        atomicMax(&rmax[r0],     __float_as_uint(lm0));
        atomicMax(&rmax[r0 + 8], __float_as_uint(lm1));
        __syncthreads();
        if (tid < 64) {
            const float m = __uint_as_float(rmax[tid]);
            sqs[tid]   = (m > 0.f) ? 127.f / m : 0.f;
            dsOut[tid] = m * (1.f / 127.f);
            rmax[tid]  = 0u;
        }
        __syncthreads();
        const float q0s = sqs[r0], q1s = sqs[r0 + 8];
#pragma unroll
        for (int n8 = 0; n8 < N8; ++n8) {
            const int c0 = ncol0 + n8 * 8 + tq * 2;
            const int i0 = (int)rintf(__int_as_float(acc[n8][0]) * q0s);
            const int i1 = (int)rintf(__int_as_float(acc[n8][1]) * q0s);
            const int i2 = (int)rintf(__int_as_float(acc[n8][2]) * q1s);
            const int i3 = (int)rintf(__int_as_float(acc[n8][3]) * q1s);
            *(uint16_t*)(sD + r0 * DS + c0) =
                (uint16_t)((i0 & 0xFF) | ((i1 & 0xFF) << 8));
            *(uint16_t*)(sD + (r0 + 8) * DS + c0) =
                (uint16_t)((i2 & 0xFF) | ((i3 & 0xFF) << 8));
        }
        __syncthreads();                    // h visible to ALL groups' next pass
    }
}

__global__ void __launch_bounds__(512, 2)
disc_kernel(const float* __restrict__ x, const float* __restrict__ lbl,
            const float* __restrict__ b1, const float* __restrict__ b2,
            const float* __restrict__ b3, const float* __restrict__ b4,
            const float* __restrict__ W5, const float* __restrict__ b5)
{
    extern __shared__ char sm[];
    int8_t* xs = (int8_t*)(sm + SO_XS);
    int8_t* h1 = (int8_t*)(sm + SO_H1);
    int8_t* h2 = (int8_t*)(sm + SO_H2);
    int8_t* h3 = (int8_t*)(sm + SO_H3);
    char*  ring = sm + SO_RING;
    float* sbias = (float*)(sm + SO_BIAS);
    float* sw5   = (float*)(sm + SO_W5);
    float* ssw   = (float*)(sm + SO_SW);
    float* ds0   = (float*)(sm + SO_DS0);
    float* ds1   = (float*)(sm + SO_DS1);
    float* sqs   = (float*)(sm + SO_QS);
    unsigned* rmax = (unsigned*)(sm + SO_RMAX);
    float* zs  = (float*)(sm + SO_ZS);
    float* red = (float*)(sm + SO_RED);

    const int tid = threadIdx.x, wid = tid >> 5, lane = tid & 31;
    const int wm = wid >> 2, wn = wid & 3;
    const int gtid = wm * 32 + lane;
    const int P0 = blockIdx.x * 64;
    const int b  = P0 / HW_, s0 = P0 % HW_;

    stage_grp(0, ring, wn, gtid);
    stage_grp(1, ring, wn, gtid);
    stage_grp(2, ring, wn, gtid);

    for (int i = tid; i < 960; i += 512) {
        sbias[i] = (i < 64) ? b1[i] : (i < 192) ? b2[i - 64]
                 : (i < 448) ? b3[i - 192] : b4[i - 448];
        ssw[i] = g_sw[i];
    }
    if (tid < 512) sw5[tid] = W5[tid];
    if (tid < 64) { rmax[tid] = 0u; zs[tid] = 0.f; }

    // x tile: 8 threads per pixel (3 channels each), per-pixel dynamic scale
    {
        const int p = tid >> 3, q8 = tid & 7;
        float xv[3]; float m = 0.f;
#pragma unroll
        for (int j = 0; j < 3; ++j) {
            const int c = q8 * 3 + j;
            xv[j] = (c < 19) ? x[(b * 19 + c) * HW_ + s0 + p] : 0.f;
            m = fmaxf(m, fabsf(xv[j]));
        }
        m = fmaxf(m, __shfl_xor_sync(0xffffffffu, m, 1));
        m = fmaxf(m, __shfl_xor_sync(0xffffffffu, m, 2));
        m = fmaxf(m, __shfl_xor_sync(0xffffffffu, m, 4));
        const float qsx = (m > 0.f) ? 127.f / m : 0.f;
        if (q8 == 0) ds0[p] = m * (1.f / 127.f);
#pragma unroll
        for (int j = 0; j < 3; ++j) {
            const int c = q8 * 3 + j;
            if (c < 19) xs[p * 48 + c] = (int8_t)(int)rintf(xv[j] * qsx);
        }
        for (int i = tid; i < 64 * 13; i += 512) {    // zero-pad k 19..31
            const int pp = i / 13, cc = 19 + i % 13;
            xs[pp * 48 + cc] = 0;
        }
    }
    __syncthreads();        // xs/zs/sbias/ssw/sw5 visible to all groups

    int chunk = 0;
    run_pass<32,  16, 48,  80,  false>(xs, h1, ring, sbias,       ssw,       ds0, ds1, sqs, rmax,
                                       nullptr, nullptr, wn * 16, 0, chunk, wm, wn, lane, tid);
    run_pass<64,  32, 80,  144, false>(h1, h2, ring, sbias + 64,  ssw + 64,  ds1, ds0, sqs, rmax,
                                       nullptr, nullptr, wn * 32, 0, chunk, wm, wn, lane, tid);
    run_pass<128, 64, 144, 272, false>(h2, h3, ring, sbias + 192, ssw + 192, ds0, ds1, sqs, rmax,
                                       nullptr, nullptr, wn * 64, 0, chunk, wm, wn, lane, tid);

    float zacc[2] = {0.f, 0.f};
    run_pass<256, 64, 272, 1, true>(h3, nullptr, ring, sbias + 448, ssw + 448, ds1,
                                    nullptr, nullptr, nullptr, sw5, zacc,
                                    wn * 64, 0, chunk, wm, wn, lane, tid);
    run_pass<256, 64, 272, 1, true>(h3, nullptr, ring, sbias + 448, ssw + 448, ds1,
                                    nullptr, nullptr, nullptr, sw5, zacc,
                                    256 + wn * 64, 256, chunk, wm, wn, lane, tid);

    zacc[0] += __shfl_xor_sync(0xffffffffu, zacc[0], 1);
    zacc[0] += __shfl_xor_sync(0xffffffffu, zacc[0], 2);
    zacc[1] += __shfl_xor_sync(0xffffffffu, zacc[1], 1);
    zacc[1] += __shfl_xor_sync(0xffffffffu, zacc[1], 2);
    if ((lane & 3) == 0) {
        const int r0 = wm * 16 + (lane >> 2);
        atomicAdd(&zs[r0],     zacc[0]);
        atomicAdd(&zs[r0 + 8], zacc[1]);
    }
    __syncthreads();

    if (tid < 64) {
        const float z = zs[tid] + b5[0];
        const float l = lbl[P0 + tid];
        float bce = fmaxf(z, 0.f) - z * l + log1pf(expf(-fabsf(z)));
#pragma unroll
        for (int o = 16; o > 0; o >>= 1) bce += __shfl_xor_sync(0xffffffffu, bce, o);
        if (lane == 0) red[wid] = bce;
    }
    __syncthreads();
    if (tid == 0) atomicAdd(&g_acc, (double)(red[0] + red[1]));
}

__global__ void fin_kernel(float* out) {
    out[0] = (float)(g_acc * (1.0 / (double)NPIX));
}

extern "C" void kernel_launch(void* const* d_in, const int* in_sizes, int n_in,
                              void* d_out, int out_size) {
    (void)in_sizes; (void)n_in; (void)out_size;
    const float* x   = (const float*)d_in[0];
    const float* lbl = (const float*)d_in[1];
    const float* W1  = (const float*)d_in[2];
    const float* b1  = (const float*)d_in[3];
    const float* W2  = (const float*)d_in[4];
    const float* b2  = (const float*)d_in[5];
    const float* W3  = (const float*)d_in[6];
    const float* b3  = (const float*)d_in[7];
    const float* W4  = (const float*)d_in[8];
    const float* b4  = (const float*)d_in[9];
    const float* W5  = (const float*)d_in[10];
    const float* b5  = (const float*)d_in[11];

    cudaFuncSetAttribute(disc_kernel, cudaFuncAttributeMaxDynamicSharedMemorySize, SMEM_BYTES);

    prep_kernel<<<120, 256>>>(W1, W2, W3, W4);
    disc_kernel<<<NPIX / 64, 512, SMEM_BYTES>>>(x, lbl, b1, b2, b3, b4, W5, b5);
    fin_kernel<<<1, 1>>>((float*)d_out);
}

// round 12
// speedup vs baseline: 1.0525x; 1.0525x over previous
#include <cuda_runtime.h>
#include <cstdint>

// ---------------------------------------------------------------------------
// Fused per-pixel MLP discriminator + BCE mean — INT8 IMMA version, R12.
//   x[4,19,256,512] -> 1x1 convs 19->64->128->256->512->1 (leaky 0.2) -> BCE mean
// disc: CTA = 64 pixels, 512 threads = 4 M-tiles x 4 N-slices, 2 CTAs/SM.
// R12 (base = R10): x tile loaded via cp.async (coalesced, staged fp32 in the
//   h3 region); L1+L2 weights resident in static SMEM (barrier-free small
//   passes); ring streams 20 uniform 8KB chunks (L3+L4); requant row-max via
//   quad-shfl + plain stores (no atomics); lbl/b5 loads hoisted to prologue.
// mma.sync m16n8k32.s8; per-col weight scales + prefix-scan error-feedback
// rounding; per-pixel dynamic activation scales; fp32 epilogues; L4+5 fused.
// ---------------------------------------------------------------------------

#define HW_   (256 * 512)
#define NPIX  (4 * HW_)
#define LEAK  0.2f

#define NRING      20          // L3: 4 chunks, L4: 16 chunks (all 8192B)
#define SLOT_BYTES 8192

__device__ __align__(16) int8_t g_Wpk[174080];
__device__ float g_sw[960];
__device__ double g_acc;

// One WARP per output column; q_k = rint(cumsum_k) - rint(cumsum_{k-1}).
__global__ void prep_kernel(const float* __restrict__ W1, const float* __restrict__ W2,
                            const float* __restrict__ W3, const float* __restrict__ W4) {
    const int lane = threadIdx.x & 31;
    const int col = blockIdx.x * 8 + (threadIdx.x >> 5);
    if (col == 0 && lane == 0) g_acc = 0.0;
    if (col >= 960) return;

    const float* Wrow; int K, nc, layer;
    if (col < 64)       { layer = 0; nc = col;       K = 19;  Wrow = W1 + nc * 19;  }
    else if (col < 192) { layer = 1; nc = col - 64;  K = 64;  Wrow = W2 + nc * 64;  }
    else if (col < 448) { layer = 2; nc = col - 192; K = 128; Wrow = W3 + nc * 128; }
    else                { layer = 3; nc = col - 448; K = 256; Wrow = W4 + nc * 256; }

    float v[8]; float m = 0.f;
#pragma unroll
    for (int j = 0; j < 8; ++j) {
        const int k = lane * 8 + j;
        v[j] = (k < K) ? Wrow[k] : 0.f;
        m = fmaxf(m, fabsf(v[j]));
    }
#pragma unroll
    for (int o = 16; o > 0; o >>= 1) m = fmaxf(m, __shfl_xor_sync(0xffffffffu, m, o));
    const float qsc = (m > 0.f) ? 127.f / m : 0.f;

    float p[8]; float s = 0.f;
#pragma unroll
    for (int j = 0; j < 8; ++j) { s += v[j] * qsc; p[j] = s; }

    float inc = s;
#pragma unroll
    for (int o = 1; o < 32; o <<= 1) {
        const float t = __shfl_up_sync(0xffffffffu, inc, o);
        if (lane >= o) inc += t;
    }
    const float base = inc - s;

    float Rprev = rintf(base);
    const int Kp = (layer == 0) ? 32 : K;
#pragma unroll
    for (int j = 0; j < 8; ++j) {
        const int k = lane * 8 + j;
        if (k >= Kp) break;
        const float R = rintf(base + p[j]);
        float q = R - Rprev;
        Rprev = R;
        q = fminf(127.f, fmaxf(-127.f, q));
        const int8_t qb = (k < K) ? (int8_t)(int)q : (int8_t)0;

        int bse, ncl = nc;
        if (layer == 0)      bse = 0;
        else if (layer == 1) bse = 2048  + (k >> 5) * 4096;
        else if (layer == 2) bse = 10240 + (k >> 5) * 8192;
        else { bse = 43008 + ((nc >> 8) * 8 + (k >> 5)) * 8192; ncl = nc & 255; }
        const int kl = k & 31, tq = (kl >> 2) & 3, hi = kl >> 4, jj = kl & 3;
        g_Wpk[bse + (ncl * 4 + tq) * 8 + hi * 4 + jj] = qb;
    }
    if (lane == 0) g_sw[col] = (m > 0.f) ? m * (1.f / 127.f) : 0.f;
}

__device__ __forceinline__ float leaky(float v) { return fmaxf(v, LEAK * v); }

__device__ __forceinline__ void imma(int* c, const uint32_t* a, uint32_t b0, uint32_t b1) {
    asm volatile(
        "mma.sync.aligned.m16n8k32.row.col.s32.s8.s8.s32 "
        "{%0,%1,%2,%3},{%4,%5,%6,%7},{%8,%9},{%0,%1,%2,%3};\n"
        : "+r"(c[0]), "+r"(c[1]), "+r"(c[2]), "+r"(c[3])
        : "r"(a[0]), "r"(a[1]), "r"(a[2]), "r"(a[3]), "r"(b0), "r"(b1));
}

__device__ __forceinline__ void cp_async16(void* dst, const void* src) {
    const uint32_t d = (uint32_t)__cvta_generic_to_shared(dst);
    asm volatile("cp.async.cg.shared.global [%0], [%1], 16;\n" :: "r"(d), "l"(src) : "memory");
}
__device__ __forceinline__ void cp_commit() {
    asm volatile("cp.async.commit_group;\n" ::: "memory");
}
template <int N> __device__ __forceinline__ void cp_wait() {
    asm volatile("cp.async.wait_group %0;\n" :: "n"(N) : "memory");
}

// Ring chunk c GMEM offset: L3 chunks 0..3 at 10240+, L4 chunks 4..19 at 43008+.
__device__ __forceinline__ int ring_off(int c) {
    return (c < 4) ? 10240 + c * 8192 : 43008 + (c - 4) * 8192;
}

// Stage ring chunk c (8192B, exactly one cp.async16 per thread).
__device__ __forceinline__ void stage_chunk(int c, char* ring, int tid) {
    if (c < NRING) {
        char* dst = ring + (c & 3) * SLOT_BYTES;
        const char* src = (const char*)g_Wpk + ring_off(c);
        cp_async16(dst + tid * 16, src + tid * 16);
    }
    cp_commit();
}

// SMEM offsets (bytes). Activation strides 48/80/144/272: conflict-free ldmatrix.
#define SO_XS     0         //  3072
#define SO_H1     3072      //  5120
#define SO_H2     8192      //  9216
#define SO_H3     17408     // 17408  (prologue: aliased as fp32 x staging, 4864B)
#define SO_STATIC 34816     // 10240  (L1+L2 weights, resident)
#define SO_RING   45056     // 32768
#define SO_BIAS   77824     //  3840
#define SO_W5     81664     //  2048
#define SO_SW     83712     //  3840
#define SO_DS0    87552     //   256
#define SO_DS1    87808     //   256
#define SO_QS     88064     //   256
#define SO_RMAX4  88320     //  1024  (float rmax[64][4])
#define SO_ZS     89344     //   256
#define SO_RED    89600     //    64
#define SMEM_BYTES 89664

// One GEMM pass, M=64: warp wm owns m16 tile rows [wm*16,+16), wn owns NW cols.
// RING=false: weights read from static SMEM (wst + cc*wstride), no barriers in
// the mainloop. RING=true: 4-slot ring streaming with per-chunk CTA barrier.
// Non-FUSE epilogue ends with a barrier (sD visible to the next pass).
template <int KP, int NW, int SS, int DS, bool FUSE, bool RING>
__device__ __forceinline__ void run_pass(
    const int8_t* sA, int8_t* sD, char* ring, const char* wst, int wstride,
    const float* __restrict__ bias, const float* __restrict__ swc,
    const float* saIn, float* dsOut, float* sqs, float* rmax4,
    const float* w5, float* zacc,
    int ncol0, int chunk_col0, int& chunk, int wm, int wn, int lane, int tid)
{
    constexpr int N8 = NW / 8;
    const int g = lane >> 2, tq = lane & 3;

    int acc[N8][4];
#pragma unroll
    for (int n = 0; n < N8; ++n)
#pragma unroll
        for (int q = 0; q < 4; ++q) acc[n][q] = 0;

    const uint32_t abase = (uint32_t)__cvta_generic_to_shared(
        sA + (wm * 16 + (lane & 15)) * SS) + ((lane >> 4) << 4);
    const int wbase = (ncol0 - chunk_col0) * 4 + tq;

#pragma unroll 1
    for (int cc = 0; cc < KP / 32; ++cc) {
        const char* slot;
        if (RING) {
            cp_wait<2>();
            __syncthreads();                   // slot (chunk-1) fully consumed
            stage_chunk(chunk + 3, ring, tid);
            slot = ring + (chunk & 3) * SLOT_BYTES;
        } else {
            slot = wst + cc * wstride;
        }

        uint32_t a[4];
        asm volatile("ldmatrix.sync.aligned.m8n8.x4.shared.b16 {%0,%1,%2,%3},[%4];\n"
            : "=r"(a[0]), "=r"(a[1]), "=r"(a[2]), "=r"(a[3])
            : "r"(abase + cc * 32));

#pragma unroll
        for (int n8 = 0; n8 < N8; ++n8) {
            const uint2 wv = *(const uint2*)(slot + ((wbase + (n8 * 8 + g) * 4) << 3));
            imma(acc[n8], a, wv.x, wv.y);
        }
        if (RING) ++chunk;
    }

    // ---- epilogue: rows r0 (acc[.][0..1]) and r0+8 (acc[.][2..3]) ----
    const int r0 = wm * 16 + g;
    const float sa0 = saIn[r0], sa1 = saIn[r0 + 8];
    float lm0 = 0.f, lm1 = 0.f;

#pragma unroll
    for (int n8 = 0; n8 < N8; ++n8) {
        const int c0 = ncol0 + n8 * 8 + tq * 2;
        const float sw0 = swc[c0], sw1 = swc[c0 + 1];
        const float bb0 = bias[c0], bb1 = bias[c0 + 1];
        const float v0 = leaky(fmaf((float)acc[n8][0], sa0 * sw0, bb0));
        const float v1 = leaky(fmaf((float)acc[n8][1], sa0 * sw1, bb1));
        const float v2 = leaky(fmaf((float)acc[n8][2], sa1 * sw0, bb0));
        const float v3 = leaky(fmaf((float)acc[n8][3], sa1 * sw1, bb1));
        if (FUSE) {
            const float w50 = w5[c0], w51 = w5[c0 + 1];
            zacc[0] += v0 * w50 + v1 * w51;
            zacc[1] += v2 * w50 + v3 * w51;
        } else {
            lm0 = fmaxf(lm0, fmaxf(fabsf(v0), fabsf(v1)));
            lm1 = fmaxf(lm1, fmaxf(fabsf(v2), fabsf(v3)));
            acc[n8][0] = __float_as_int(v0); acc[n8][1] = __float_as_int(v1);
            acc[n8][2] = __float_as_int(v2); acc[n8][3] = __float_as_int(v3);
        }
    }

    if (!FUSE) {
        // Row max: reduce over the quad (tq lanes), one plain store per (row,wn).
        lm0 = fmaxf(lm0, __shfl_xor_sync(0xffffffffu, lm0, 1));
        lm0 = fmaxf(lm0, __shfl_xor_sync(0xffffffffu, lm0, 2));
        lm1 = fmaxf(lm1, __shfl_xor_sync(0xffffffffu, lm1, 1));
        lm1 = fmaxf(lm1, __shfl_xor_sync(0xffffffffu, lm1, 2));
        if (tq == 0) {
            rmax4[r0 * 4 + wn]       = lm0;
            rmax4[(r0 + 8) * 4 + wn] = lm1;
        }
        __syncthreads();
        if (tid < 64) {
            const float m = fmaxf(fmaxf(rmax4[tid * 4 + 0], rmax4[tid * 4 + 1]),
                                  fmaxf(rmax4[tid * 4 + 2], rmax4[tid * 4 + 3]));
            sqs[tid]   = (m > 0.f) ? 127.f / m : 0.f;
            dsOut[tid] = m * (1.f / 127.f);
        }
        __syncthreads();
        const float q0s = sqs[r0], q1s = sqs[r0 + 8];
#pragma unroll
        for (int n8 = 0; n8 < N8; ++n8) {
            const int c0 = ncol0 + n8 * 8 + tq * 2;
            const int i0 = (int)rintf(__int_as_float(acc[n8][0]) * q0s);
            const int i1 = (int)rintf(__int_as_float(acc[n8][1]) * q0s);
            const int i2 = (int)rintf(__int_as_float(acc[n8][2]) * q1s);
            const int i3 = (int)rintf(__int_as_float(acc[n8][3]) * q1s);
            *(uint16_t*)(sD + r0 * DS + c0) =
                (uint16_t)((i0 & 0xFF) | ((i1 & 0xFF) << 8));
            *(uint16_t*)(sD + (r0 + 8) * DS + c0) =
                (uint16_t)((i2 & 0xFF) | ((i3 & 0xFF) << 8));
        }
        __syncthreads();                       // sD visible to the next pass
    }
}

__global__ void __launch_bounds__(512, 2)
disc_kernel(const float* __restrict__ x, const float* __restrict__ lbl,
            const float* __restrict__ b1, const float* __restrict__ b2,
            const float* __restrict__ b3, const float* __restrict__ b4,
            const float* __restrict__ W5, const float* __restrict__ b5)
{
    extern __shared__ char sm[];
    int8_t* xs = (int8_t*)(sm + SO_XS);
    int8_t* h1 = (int8_t*)(sm + SO_H1);
    int8_t* h2 = (int8_t*)(sm + SO_H2);
    int8_t* h3 = (int8_t*)(sm + SO_H3);
    float* xstage = (float*)(sm + SO_H3);      // prologue alias: [19][64] fp32
    char*  wstatic = sm + SO_STATIC;
    char*  ring = sm + SO_RING;
    float* sbias = (float*)(sm + SO_BIAS);
    float* sw5   = (float*)(sm + SO_W5);
    float* ssw   = (float*)(sm + SO_SW);
    float* ds0   = (float*)(sm + SO_DS0);
    float* ds1   = (float*)(sm + SO_DS1);
    float* sqs   = (float*)(sm + SO_QS);
    float* rmax4 = (float*)(sm + SO_RMAX4);
    float* zs  = (float*)(sm + SO_ZS);
    float* red = (float*)(sm + SO_RED);

    const int tid = threadIdx.x, wid = tid >> 5, lane = tid & 31;
    const int wm = wid >> 2, wn = wid & 3;
    const int P0 = blockIdx.x * 64;
    const int b  = P0 / HW_, s0 = P0 % HW_;

    // ---- G0: x tile (fp32, coalesced) + static L1/L2 weights ----
    if (tid < 304) {                            // 19 ch x 16 x 16B (64 px fp32)
        const int c = tid >> 4, seg = tid & 15;
        cp_async16((char*)xstage + c * 256 + seg * 16,
                   (const char*)(x + (size_t)(b * 19 + c) * HW_ + s0) + seg * 16);
    }
    for (int off = tid * 16; off < 10240; off += 512 * 16)
        cp_async16(wstatic + off, (const char*)g_Wpk + off);
    cp_commit();
    stage_chunk(0, ring, tid);                  // G1..G3: L3 chunks 0..2
    stage_chunk(1, ring, tid);
    stage_chunk(2, ring, tid);

    // Const staging + hoisted tail loads (overlap with cp.async).
    for (int i = tid; i < 960; i += 512) {
        sbias[i] = (i < 64) ? b1[i] : (i < 192) ? b2[i - 64]
                 : (i < 448) ? b3[i - 192] : b4[i - 448];
        ssw[i] = g_sw[i];
    }
    sw5[tid] = W5[tid];
    const float lblv = (tid < 64) ? lbl[P0 + tid] : 0.f;
    const float b5v  = b5[0];
    if (tid < 64) zs[tid] = 0.f;

    cp_wait<3>();                               // G0 done: xstage + wstatic ready
    __syncthreads();

    // Quantize x: 8 threads per pixel (3 channels each), per-pixel scale.
    {
        const int p = tid >> 3, q8 = tid & 7;
        float xv[3]; float m = 0.f;
#pragma unroll
        for (int j = 0; j < 3; ++j) {
            const int c = q8 * 3 + j;
            xv[j] = (c < 19) ? xstage[c * 64 + p] : 0.f;
            m = fmaxf(m, fabsf(xv[j]));
        }
        m = fmaxf(m, __shfl_xor_sync(0xffffffffu, m, 1));
        m = fmaxf(m, __shfl_xor_sync(0xffffffffu, m, 2));
        m = fmaxf(m, __shfl_xor_sync(0xffffffffu, m, 4));
        const float qsx = (m > 0.f) ? 127.f / m : 0.f;
        if (q8 == 0) ds0[p] = m * (1.f / 127.f);
#pragma unroll
        for (int j = 0; j < 3; ++j) {
            const int c = q8 * 3 + j;
            if (c < 19) xs[p * 48 + c] = (int8_t)(int)rintf(xv[j] * qsx);
        }
        for (int i = tid; i < 64 * 13; i += 512) {   // zero-pad k 19..31
            const int pp = i / 13, cc = 19 + i % 13;
            xs[pp * 48 + cc] = 0;
        }
    }
    __syncthreads();                            // xs + consts visible

    int chunk = 0;
    // L1 (static, 1 chunk) and L2 (static, 2 chunks): barrier-free mainloops.
    run_pass<32,  16, 48,  80,  false, false>(xs, h1, ring, wstatic,        0,
        sbias,       ssw,       ds0, ds1, sqs, rmax4, nullptr, nullptr,
        wn * 16, 0, chunk, wm, wn, lane, tid);
    run_pass<64,  32, 80,  144, false, false>(h1, h2, ring, wstatic + 2048, 4096,
        sbias + 64,  ssw + 64,  ds1, ds0, sqs, rmax4, nullptr, nullptr,
        wn * 32, 0, chunk, wm, wn, lane, tid);
    // L3 (ring chunks 0..3) and L4 (ring chunks 4..19).
    run_pass<128, 64, 144, 272, false, true>(h2, h3, ring, nullptr, 0,
        sbias + 192, ssw + 192, ds0, ds1, sqs, rmax4, nullptr, nullptr,
        wn * 64, 0, chunk, wm, wn, lane, tid);

    float zacc[2] = {0.f, 0.f};
    run_pass<256, 64, 272, 1, true, true>(h3, nullptr, ring, nullptr, 0,
        sbias + 448, ssw + 448, ds1, nullptr, nullptr, nullptr, sw5, zacc,
        wn * 64, 0, chunk, wm, wn, lane, tid);
    run_pass<256, 64, 272, 1, true, true>(h3, nullptr, ring, nullptr, 0,
        sbias + 448, ssw + 448, ds1, nullptr, nullptr, nullptr, sw5, zacc,
        256 + wn * 64, 256, chunk, wm, wn, lane, tid);

    zacc[0] += __shfl_xor_sync(0xffffffffu, zacc[0], 1);
    zacc[0] += __shfl_xor_sync(0xffffffffu, zacc[0], 2);
    zacc[1] += __shfl_xor_sync(0xffffffffu, zacc[1], 1);
    zacc[1] += __shfl_xor_sync(0xffffffffu, zacc[1], 2);
    if ((lane & 3) == 0) {
        const int r0 = wm * 16 + (lane >> 2);
        atomicAdd(&zs[r0],     zacc[0]);
        atomicAdd(&zs[r0 + 8], zacc[1]);
    }
    __syncthreads();

    if (tid < 64) {
        const float z = zs[tid] + b5v;
        float bce = fmaxf(z, 0.f) - z * lblv + log1pf(expf(-fabsf(z)));
#pragma unroll
        for (int o = 16; o > 0; o >>= 1) bce += __shfl_xor_sync(0xffffffffu, bce, o);
        if (lane == 0) red[wid] = bce;
    }
    __syncthreads();
    if (tid == 0) atomicAdd(&g_acc, (double)(red[0] + red[1]));
}

__global__ void fin_kernel(float* out) {
    out[0] = (float)(g_acc * (1.0 / (double)NPIX));
}

extern "C" void kernel_launch(void* const* d_in, const int* in_sizes, int n_in,
                              void* d_out, int out_size) {
    (void)in_sizes; (void)n_in; (void)out_size;
    const float* x   = (const float*)d_in[0];
    const float* lbl = (const float*)d_in[1];
    const float* W1  = (const float*)d_in[2];
    const float* b1  = (const float*)d_in[3];
    const float* W2  = (const float*)d_in[4];
    const float* b2  = (const float*)d_in[5];
    const float* W3  = (const float*)d_in[6];
    const float* b3  = (const float*)d_in[7];
    const float* W4  = (const float*)d_in[8];
    const float* b4  = (const float*)d_in[9];
    const float* W5  = (const float*)d_in[10];
    const float* b5  = (const float*)d_in[11];

    cudaFuncSetAttribute(disc_kernel, cudaFuncAttributeMaxDynamicSharedMemorySize, SMEM_BYTES);

    prep_kernel<<<120, 256>>>(W1, W2, W3, W4);
    disc_kernel<<<NPIX / 64, 512, SMEM_BYTES>>>(x, lbl, b1, b2, b3, b4, W5, b5);
    fin_kernel<<<1, 1>>>((float*)d_out);
}

// round 15
// speedup vs baseline: 1.0579x; 1.0051x over previous
#include <cuda_runtime.h>
#include <cstdint>

// ---------------------------------------------------------------------------
// Fused per-pixel MLP discriminator + BCE mean — INT8 IMMA, persistent (R15).
//   x[4,19,256,512] -> 1x1 convs 19->64->128->256->512->1 (leaky 0.2) -> BCE mean
// disc: PERSISTENT grid of 296 CTAs (2/SM); each CTA loops over tiles of 64
//   pixels (tile += 296). Prologue (static L1/L2 weights, biases/scales) runs
//   once per CTA; the 4-slot cp.async weight ring runs CONTINUOUSLY across
//   tiles (global chunk counter, period-20 source map, 20%4==0 keeps slots
//   consistent); next tile's x is prefetched into registers mid-tile.
// mma.sync m16n8k32.s8; per-col weight scales + prefix-scan error-feedback
// rounding; per-pixel dynamic activation scales; fp32 epilogues; L4+5 fused.
// BCE accumulated per-thread (double) across tiles; one atomicAdd per CTA.
// ---------------------------------------------------------------------------

#define HW_   (256 * 512)
#define NPIX  (4 * HW_)
#define NT    (NPIX / 64)      // 8192 tiles
#define GRIDP 296              // 148 SMs x 2 CTAs
#define LEAK  0.2f

#define SLOT_BYTES 8192

__device__ __align__(16) int8_t g_Wpk[174080];
__device__ float g_sw[960];
__device__ double g_acc;

// One WARP per output column; q_k = rint(cumsum_k) - rint(cumsum_{k-1}).
__global__ void prep_kernel(const float* __restrict__ W1, const float* __restrict__ W2,
                            const float* __restrict__ W3, const float* __restrict__ W4) {
    const int lane = threadIdx.x & 31;
    const int col = blockIdx.x * 8 + (threadIdx.x >> 5);
    if (col == 0 && lane == 0) g_acc = 0.0;
    if (col >= 960) return;

    const float* Wrow; int K, nc, layer;
    if (col < 64)       { layer = 0; nc = col;       K = 19;  Wrow = W1 + nc * 19;  }
    else if (col < 192) { layer = 1; nc = col - 64;  K = 64;  Wrow = W2 + nc * 64;  }
    else if (col < 448) { layer = 2; nc = col - 192; K = 128; Wrow = W3 + nc * 128; }
    else                { layer = 3; nc = col - 448; K = 256; Wrow = W4 + nc * 256; }

    float v[8]; float m = 0.f;
#pragma unroll
    for (int j = 0; j < 8; ++j) {
        const int k = lane * 8 + j;
        v[j] = (k < K) ? Wrow[k] : 0.f;
        m = fmaxf(m, fabsf(v[j]));
    }
#pragma unroll
    for (int o = 16; o > 0; o >>= 1) m = fmaxf(m, __shfl_xor_sync(0xffffffffu, m, o));
    const float qsc = (m > 0.f) ? 127.f / m : 0.f;

    float p[8]; float s = 0.f;
#pragma unroll
    for (int j = 0; j < 8; ++j) { s += v[j] * qsc; p[j] = s; }

    float inc = s;
#pragma unroll
    for (int o = 1; o < 32; o <<= 1) {
        const float t = __shfl_up_sync(0xffffffffu, inc, o);
        if (lane >= o) inc += t;
    }
    const float base = inc - s;

    float Rprev = rintf(base);
    const int Kp = (layer == 0) ? 32 : K;
#pragma unroll
    for (int j = 0; j < 8; ++j) {
        const int k = lane * 8 + j;
        if (k >= Kp) break;
        const float R = rintf(base + p[j]);
        float q = R - Rprev;
        Rprev = R;
        q = fminf(127.f, fmaxf(-127.f, q));
        const int8_t qb = (k < K) ? (int8_t)(int)q : (int8_t)0;

        int bse, ncl = nc;
        if (layer == 0)      bse = 0;
        else if (layer == 1) bse = 2048  + (k >> 5) * 4096;
        else if (layer == 2) bse = 10240 + (k >> 5) * 8192;
        else { bse = 43008 + ((nc >> 8) * 8 + (k >> 5)) * 8192; ncl = nc & 255; }
        const int kl = k & 31, tq = (kl >> 2) & 3, hi = kl >> 4, jj = kl & 3;
        g_Wpk[bse + (ncl * 4 + tq) * 8 + hi * 4 + jj] = qb;
    }
    if (lane == 0) g_sw[col] = (m > 0.f) ? m * (1.f / 127.f) : 0.f;
}

__device__ __forceinline__ float leaky(float v) { return fmaxf(v, LEAK * v); }

__device__ __forceinline__ void imma(int* c, const uint32_t* a, uint32_t b0, uint32_t b1) {
    asm volatile(
        "mma.sync.aligned.m16n8k32.row.col.s32.s8.s8.s32 "
        "{%0,%1,%2,%3},{%4,%5,%6,%7},{%8,%9},{%0,%1,%2,%3};\n"
        : "+r"(c[0]), "+r"(c[1]), "+r"(c[2]), "+r"(c[3])
        : "r"(a[0]), "r"(a[1]), "r"(a[2]), "r"(a[3]), "r"(b0), "r"(b1));
}

__device__ __forceinline__ void cp_async16(void* dst, const void* src) {
    const uint32_t d = (uint32_t)__cvta_generic_to_shared(dst);
    asm volatile("cp.async.cg.shared.global [%0], [%1], 16;\n" :: "r"(d), "l"(src) : "memory");
}
__device__ __forceinline__ void cp_commit() {
    asm volatile("cp.async.commit_group;\n" ::: "memory");
}
template <int N> __device__ __forceinline__ void cp_wait() {
    asm volatile("cp.async.wait_group %0;\n" :: "n"(N) : "memory");
}

// Ring source map, period 20: L3 chunks 0..3 at 10240+, L4 4..19 at 43008+.
__device__ __forceinline__ int ring_off(int c20) {
    return (c20 < 4) ? 10240 + c20 * 8192 : 43008 + (c20 - 4) * 8192;
}

// Stage ring chunk with GLOBAL counter c (slot c&3, source ring_off(c%20)).
// 8192B = exactly one cp.async16 per thread. Runs continuously across tiles.
__device__ __forceinline__ void stage_chunk(int c, char* ring, int tid) {
    char* dst = ring + (c & 3) * SLOT_BYTES;
    const char* src = (const char*)g_Wpk + ring_off(c % 20);
    cp_async16(dst + tid * 16, src + tid * 16);
    cp_commit();
}

// SMEM offsets (bytes). Activation strides 48/80/144/272: conflict-free ldmatrix.
#define SO_XS     0         //  3072
#define SO_H1     3072      //  5120
#define SO_H2     8192      //  9216
#define SO_H3     17408     // 17408
#define SO_XSTAGE 34816     //  4864  (fp32 x tile [19][64], own buffer)
#define SO_STATIC 39680     // 10240  (L1+L2 weights, resident)
#define SO_RING   49920     // 32768
#define SO_BIAS   82688     //  3840
#define SO_W5     86528     //  2048
#define SO_SW     88576     //  3840
#define SO_DS0    92416     //   256
#define SO_DS1    92672     //   256
#define SO_QS     92928     //   256
#define SO_RMAX4  93184     //  1024  (float rmax[64][4]; reused as double red[64])
#define SO_ZS     94208     //   256
#define SMEM_BYTES 94464

// One GEMM pass, M=64 (identical math to R12).
template <int KP, int NW, int SS, int DS, bool FUSE, bool RING>
__device__ __forceinline__ void run_pass(
    const int8_t* sA, int8_t* sD, char* ring, const char* wst, int wstride,
    const float* __restrict__ bias, const float* __restrict__ swc,
    const float* saIn, float* dsOut, float* sqs, float* rmax4,
    const float* w5, float* zacc,
    int ncol0, int chunk_col0, int& chunk, int wm, int wn, int lane, int tid)
{
    constexpr int N8 = NW / 8;
    const int g = lane >> 2, tq = lane & 3;

    int acc[N8][4];
#pragma unroll
    for (int n = 0; n < N8; ++n)
#pragma unroll
        for (int q = 0; q < 4; ++q) acc[n][q] = 0;

    const uint32_t abase = (uint32_t)__cvta_generic_to_shared(
        sA + (wm * 16 + (lane & 15)) * SS) + ((lane >> 4) << 4);
    const int wbase = (ncol0 - chunk_col0) * 4 + tq;

#pragma unroll 1
    for (int cc = 0; cc < KP / 32; ++cc) {
        const char* slot;
        if (RING) {
            cp_wait<2>();
            __syncthreads();                   // slot (chunk-1) fully consumed
            stage_chunk(chunk + 3, ring, tid);
            slot = ring + (chunk & 3) * SLOT_BYTES;
        } else {
            slot = wst + cc * wstride;
        }

        uint32_t a[4];
        asm volatile("ldmatrix.sync.aligned.m8n8.x4.shared.b16 {%0,%1,%2,%3},[%4];\n"
            : "=r"(a[0]), "=r"(a[1]), "=r"(a[2]), "=r"(a[3])
            : "r"(abase + cc * 32));

#pragma unroll
        for (int n8 = 0; n8 < N8; ++n8) {
            const uint2 wv = *(const uint2*)(slot + ((wbase + (n8 * 8 + g) * 4) << 3));
            imma(acc[n8], a, wv.x, wv.y);
        }
        if (RING) ++chunk;
    }

    // ---- epilogue: rows r0 (acc[.][0..1]) and r0+8 (acc[.][2..3]) ----
    const int r0 = wm * 16 + g;
    const float sa0 = saIn[r0], sa1 = saIn[r0 + 8];
    float lm0 = 0.f, lm1 = 0.f;

#pragma unroll
    for (int n8 = 0; n8 < N8; ++n8) {
        const int c0 = ncol0 + n8 * 8 + tq * 2;
        const float sw0 = swc[c0], sw1 = swc[c0 + 1];
        const float bb0 = bias[c0], bb1 = bias[c0 + 1];
        const float v0 = leaky(fmaf((float)acc[n8][0], sa0 * sw0, bb0));
        const float v1 = leaky(fmaf((float)acc[n8][1], sa0 * sw1, bb1));
        const float v2 = leaky(fmaf((float)acc[n8][2], sa1 * sw0, bb0));
        const float v3 = leaky(fmaf((float)acc[n8][3], sa1 * sw1, bb1));
        if (FUSE) {
            const float w50 = w5[c0], w51 = w5[c0 + 1];
            zacc[0] += v0 * w50 + v1 * w51;
            zacc[1] += v2 * w50 + v3 * w51;
        } else {
            lm0 = fmaxf(lm0, fmaxf(fabsf(v0), fabsf(v1)));
            lm1 = fmaxf(lm1, fmaxf(fabsf(v2), fabsf(v3)));
            acc[n8][0] = __float_as_int(v0); acc[n8][1] = __float_as_int(v1);
            acc[n8][2] = __float_as_int(v2); acc[n8][3] = __float_as_int(v3);
        }
    }

    if (!FUSE) {
        lm0 = fmaxf(lm0, __shfl_xor_sync(0xffffffffu, lm0, 1));
        lm0 = fmaxf(lm0, __shfl_xor_sync(0xffffffffu, lm0, 2));
        lm1 = fmaxf(lm1, __shfl_xor_sync(0xffffffffu, lm1, 1));
        lm1 = fmaxf(lm1, __shfl_xor_sync(0xffffffffu, lm1, 2));
        if (tq == 0) {
            rmax4[r0 * 4 + wn]       = lm0;
            rmax4[(r0 + 8) * 4 + wn] = lm1;
        }
        __syncthreads();
        if (tid < 64) {
            const float m = fmaxf(fmaxf(rmax4[tid * 4 + 0], rmax4[tid * 4 + 1]),
                                  fmaxf(rmax4[tid * 4 + 2], rmax4[tid * 4 + 3]));
            sqs[tid]   = (m > 0.f) ? 127.f / m : 0.f;
            dsOut[tid] = m * (1.f / 127.f);
        }
        __syncthreads();
        const float q0s = sqs[r0], q1s = sqs[r0 + 8];
#pragma unroll
        for (int n8 = 0; n8 < N8; ++n8) {
            const int c0 = ncol0 + n8 * 8 + tq * 2;
            const int i0 = (int)rintf(__int_as_float(acc[n8][0]) * q0s);
            const int i1 = (int)rintf(__int_as_float(acc[n8][1]) * q0s);
            const int i2 = (int)rintf(__int_as_float(acc[n8][2]) * q1s);
            const int i3 = (int)rintf(__int_as_float(acc[n8][3]) * q1s);
            *(uint16_t*)(sD + r0 * DS + c0) =
                (uint16_t)((i0 & 0xFF) | ((i1 & 0xFF) << 8));
            *(uint16_t*)(sD + (r0 + 8) * DS + c0) =
                (uint16_t)((i2 & 0xFF) | ((i3 & 0xFF) << 8));
        }
        __syncthreads();                       // sD visible to the next pass
    }
}

__global__ void __launch_bounds__(512, 2)
disc_kernel(const float* __restrict__ x, const float* __restrict__ lbl,
            const float* __restrict__ b1, const float* __restrict__ b2,
            const float* __restrict__ b3, const float* __restrict__ b4,
            const float* __restrict__ W5, const float* __restrict__ b5)
{
    extern __shared__ char sm[];
    int8_t* xs = (int8_t*)(sm + SO_XS);
    int8_t* h1 = (int8_t*)(sm + SO_H1);
    int8_t* h2 = (int8_t*)(sm + SO_H2);
    int8_t* h3 = (int8_t*)(sm + SO_H3);
    float* xstage = (float*)(sm + SO_XSTAGE);  // [19][64] fp32
    char*  wstatic = sm + SO_STATIC;
    char*  ring = sm + SO_RING;
    float* sbias = (float*)(sm + SO_BIAS);
    float* sw5   = (float*)(sm + SO_W5);
    float* ssw   = (float*)(sm + SO_SW);
    float* ds0   = (float*)(sm + SO_DS0);
    float* ds1   = (float*)(sm + SO_DS1);
    float* sqs   = (float*)(sm + SO_QS);
    float* rmax4 = (float*)(sm + SO_RMAX4);
    float* zs  = (float*)(sm + SO_ZS);

    const int tid = threadIdx.x, wid = tid >> 5, lane = tid & 31;
    const int wm = wid >> 2, wn = wid & 3;

    // ---- once-per-CTA prologue ----
    for (int off = tid * 16; off < 10240; off += 512 * 16)      // static L1/L2 w
        cp_async16(wstatic + off, (const char*)g_Wpk + off);
    cp_commit();
    stage_chunk(0, ring, tid);                                   // ring spin-up
    stage_chunk(1, ring, tid);
    stage_chunk(2, ring, tid);

    for (int i = tid; i < 960; i += 512) {
        sbias[i] = (i < 64) ? b1[i] : (i < 192) ? b2[i - 64]
                 : (i < 448) ? b3[i - 192] : b4[i - 448];
        ssw[i] = g_sw[i];
    }
    sw5[tid] = W5[tid];
    const float b5v = b5[0];

    // x prefetch for first tile: one uint4 per thread (tid<304 = 19ch x 16seg).
    const int xc = tid >> 4, xseg = tid & 15;
    uint4 xreg = make_uint4(0, 0, 0, 0);
    {
        const int P0 = blockIdx.x * 64;
        if (tid < 304)
            xreg = *(const uint4*)((const char*)
                (x + (size_t)((P0 / HW_) * 19 + xc) * HW_ + (P0 % HW_)) + xseg * 16);
    }
    cp_wait<3>();                               // wstatic group done
    __syncthreads();

    double bce_acc = 0.0;
    int chunk = 0;

    for (int tile = blockIdx.x; tile < NT; tile += GRIDP) {
        const int P0 = tile * 64;

        // Spill x regs to SMEM; zero zs; load this tile's labels (in flight).
        if (tid < 304) *(uint4*)((char*)xstage + tid * 16) = xreg;
        float lblv = 0.f;
        if (tid < 64) { zs[tid] = 0.f; lblv = lbl[P0 + tid]; }
        __syncthreads();

        // Quantize x: 8 threads/pixel, per-pixel dynamic scale.
        {
            const int p = tid >> 3, q8 = tid & 7;
            float xv[3]; float m = 0.f;
#pragma unroll
            for (int j = 0; j < 3; ++j) {
                const int c = q8 * 3 + j;
                xv[j] = (c < 19) ? xstage[c * 64 + p] : 0.f;
                m = fmaxf(m, fabsf(xv[j]));
            }
            m = fmaxf(m, __shfl_xor_sync(0xffffffffu, m, 1));
            m = fmaxf(m, __shfl_xor_sync(0xffffffffu, m, 2));
            m = fmaxf(m, __shfl_xor_sync(0xffffffffu, m, 4));
            const float qsx = (m > 0.f) ? 127.f / m : 0.f;
            if (q8 == 0) ds0[p] = m * (1.f / 127.f);
#pragma unroll
            for (int j = 0; j < 3; ++j) {
                const int c = q8 * 3 + j;
                if (c < 19) xs[p * 48 + c] = (int8_t)(int)rintf(xv[j] * qsx);
            }
            for (int i = tid; i < 64 * 13; i += 512) {
                const int pp = i / 13, cc = 19 + i % 13;
                xs[pp * 48 + cc] = 0;
            }
        }

        // Prefetch next tile's x into registers (hidden under this tile).
        {
            const int tn = tile + GRIDP;
            if (tid < 304 && tn < NT) {
                const int Pn = tn * 64;
                xreg = *(const uint4*)((const char*)
                    (x + (size_t)((Pn / HW_) * 19 + xc) * HW_ + (Pn % HW_)) + xseg * 16);
            }
        }
        __syncthreads();                        // xs + ds0 visible

        run_pass<32,  16, 48,  80,  false, false>(xs, h1, ring, wstatic,        0,
            sbias,       ssw,       ds0, ds1, sqs, rmax4, nullptr, nullptr,
            wn * 16, 0, chunk, wm, wn, lane, tid);
        run_pass<64,  32, 80,  144, false, false>(h1, h2, ring, wstatic + 2048, 4096,
            sbias + 64,  ssw + 64,  ds1, ds0, sqs, rmax4, nullptr, nullptr,
            wn * 32, 0, chunk, wm, wn, lane, tid);
        run_pass<128, 64, 144, 272, false, true>(h2, h3, ring, nullptr, 0,
            sbias + 192, ssw + 192, ds0, ds1, sqs, rmax4, nullptr, nullptr,
            wn * 64, 0, chunk, wm, wn, lane, tid);

        float zacc[2] = {0.f, 0.f};
        run_pass<256, 64, 272, 1, true, true>(h3, nullptr, ring, nullptr, 0,
            sbias + 448, ssw + 448, ds1, nullptr, nullptr, nullptr, sw5, zacc,
            wn * 64, 0, chunk, wm, wn, lane, tid);
        run_pass<256, 64, 272, 1, true, true>(h3, nullptr, ring, nullptr, 0,
            sbias + 448, ssw + 448, ds1, nullptr, nullptr, nullptr, sw5, zacc,
            256 + wn * 64, 256, chunk, wm, wn, lane, tid);

        zacc[0] += __shfl_xor_sync(0xffffffffu, zacc[0], 1);
        zacc[0] += __shfl_xor_sync(0xffffffffu, zacc[0], 2);
        zacc[1] += __shfl_xor_sync(0xffffffffu, zacc[1], 1);
        zacc[1] += __shfl_xor_sync(0xffffffffu, zacc[1], 2);
        if ((lane & 3) == 0) {
            const int r0 = wm * 16 + (lane >> 2);
            atomicAdd(&zs[r0],     zacc[0]);
            atomicAdd(&zs[r0 + 8], zacc[1]);
        }
        __syncthreads();

        if (tid < 64) {
            const float z = zs[tid] + b5v;
            bce_acc += (double)(fmaxf(z, 0.f) - z * lblv + log1pf(expf(-fabsf(z))));
        }
        __syncthreads();                        // zs reads done before re-zero
    }

    // ---- final reduction: one atomicAdd per CTA ----
    cp_wait<0>();                               // drain dangling ring groups
    __syncthreads();
    double* dred = (double*)(sm + SO_RMAX4);    // 64 doubles = 512B, reuse
    if (tid < 64) dred[tid] = bce_acc;
    __syncthreads();
    if (tid == 0) {
        double s = 0.0;
        for (int i = 0; i < 64; ++i) s += dred[i];
        atomicAdd(&g_acc, s);
    }
}

__global__ void fin_kernel(float* out) {
    out[0] = (float)(g_acc * (1.0 / (double)NPIX));
}

extern "C" void kernel_launch(void* const* d_in, const int* in_sizes, int n_in,
                              void* d_out, int out_size) {
    (void)in_sizes; (void)n_in; (void)out_size;
    const float* x   = (const float*)d_in[0];
    const float* lbl = (const float*)d_in[1];
    const float* W1  = (const float*)d_in[2];
    const float* b1  = (const float*)d_in[3];
    const float* W2  = (const float*)d_in[4];
    const float* b2  = (const float*)d_in[5];
    const float* W3  = (const float*)d_in[6];
    const float* b3  = (const float*)d_in[7];
    const float* W4  = (const float*)d_in[8];
    const float* b4  = (const float*)d_in[9];
    const float* W5  = (const float*)d_in[10];
    const float* b5  = (const float*)d_in[11];

    cudaFuncSetAttribute(disc_kernel, cudaFuncAttributeMaxDynamicSharedMemorySize, SMEM_BYTES);

    prep_kernel<<<120, 256>>>(W1, W2, W3, W4);
    disc_kernel<<<GRIDP, 512, SMEM_BYTES>>>(x, lbl, b1, b2, b3, b4, W5, b5);
    fin_kernel<<<1, 1>>>((float*)d_out);
}

// round 16
// speedup vs baseline: 1.1432x; 1.0806x over previous
#include <cuda_runtime.h>
#include <cstdint>

// ---------------------------------------------------------------------------
// Fused per-pixel MLP discriminator + BCE mean — INT8 IMMA, persistent (R16).
//   x[4,19,256,512] -> 1x1 convs 19->64->128->256->512->1 (leaky 0.2) -> BCE mean
// disc: PERSISTENT grid of 296 CTAs (2/SM); each CTA loops over tiles of 64
//   pixels. R16: weight ring upgraded to 16KB chunks (k64) in a 3-slot ring —
//   ring iterations per tile drop 20 -> 10 (L3:2, L4:8); each iteration does
//   two k32 sub-steps (2 ldmatrix + 32 IMMA) per warp, amortizing the barrier
//   and cp.async wait. Global chunk counter; slot = g % 3; prefetch depth 2.
// mma.sync m16n8k32.s8; per-col weight scales + prefix-scan error-feedback
// rounding; per-pixel dynamic activation scales; fp32 epilogues; L4+5 fused.
// BCE accumulated per-thread (double) across tiles; one atomicAdd per CTA.
// ---------------------------------------------------------------------------

#define HW_   (256 * 512)
#define NPIX  (4 * HW_)
#define NT    (NPIX / 64)      // 8192 tiles
#define GRIDP 296              // 148 SMs x 2 CTAs
#define LEAK  0.2f

#define SLOT_BYTES 16384       // 16KB = k64 chunk
#define NSLOT      3

__device__ __align__(16) int8_t g_Wpk[174080];
__device__ float g_sw[960];
__device__ double g_acc;

// One WARP per output column; q_k = rint(cumsum_k) - rint(cumsum_{k-1}).
__global__ void prep_kernel(const float* __restrict__ W1, const float* __restrict__ W2,
                            const float* __restrict__ W3, const float* __restrict__ W4) {
    const int lane = threadIdx.x & 31;
    const int col = blockIdx.x * 8 + (threadIdx.x >> 5);
    if (col == 0 && lane == 0) g_acc = 0.0;
    if (col >= 960) return;

    const float* Wrow; int K, nc, layer;
    if (col < 64)       { layer = 0; nc = col;       K = 19;  Wrow = W1 + nc * 19;  }
    else if (col < 192) { layer = 1; nc = col - 64;  K = 64;  Wrow = W2 + nc * 64;  }
    else if (col < 448) { layer = 2; nc = col - 192; K = 128; Wrow = W3 + nc * 128; }
    else                { layer = 3; nc = col - 448; K = 256; Wrow = W4 + nc * 256; }

    float v[8]; float m = 0.f;
#pragma unroll
    for (int j = 0; j < 8; ++j) {
        const int k = lane * 8 + j;
        v[j] = (k < K) ? Wrow[k] : 0.f;
        m = fmaxf(m, fabsf(v[j]));
    }
#pragma unroll
    for (int o = 16; o > 0; o >>= 1) m = fmaxf(m, __shfl_xor_sync(0xffffffffu, m, o));
    const float qsc = (m > 0.f) ? 127.f / m : 0.f;

    float p[8]; float s = 0.f;
#pragma unroll
    for (int j = 0; j < 8; ++j) { s += v[j] * qsc; p[j] = s; }

    float inc = s;
#pragma unroll
    for (int o = 1; o < 32; o <<= 1) {
        const float t = __shfl_up_sync(0xffffffffu, inc, o);
        if (lane >= o) inc += t;
    }
    const float base = inc - s;

    float Rprev = rintf(base);
    const int Kp = (layer == 0) ? 32 : K;
#pragma unroll
    for (int j = 0; j < 8; ++j) {
        const int k = lane * 8 + j;
        if (k >= Kp) break;
        const float R = rintf(base + p[j]);
        float q = R - Rprev;
        Rprev = R;
        q = fminf(127.f, fmaxf(-127.f, q));
        const int8_t qb = (k < K) ? (int8_t)(int)q : (int8_t)0;

        int bse, ncl = nc;
        if (layer == 0)      bse = 0;
        else if (layer == 1) bse = 2048  + (k >> 5) * 4096;
        else if (layer == 2) bse = 10240 + (k >> 5) * 8192;
        else { bse = 43008 + ((nc >> 8) * 8 + (k >> 5)) * 8192; ncl = nc & 255; }
        const int kl = k & 31, tq = (kl >> 2) & 3, hi = kl >> 4, jj = kl & 3;
        g_Wpk[bse + (ncl * 4 + tq) * 8 + hi * 4 + jj] = qb;
    }
    if (lane == 0) g_sw[col] = (m > 0.f) ? m * (1.f / 127.f) : 0.f;
}

__device__ __forceinline__ float leaky(float v) { return fmaxf(v, LEAK * v); }

__device__ __forceinline__ void imma(int* c, const uint32_t* a, uint32_t b0, uint32_t b1) {
    asm volatile(
        "mma.sync.aligned.m16n8k32.row.col.s32.s8.s8.s32 "
        "{%0,%1,%2,%3},{%4,%5,%6,%7},{%8,%9},{%0,%1,%2,%3};\n"
        : "+r"(c[0]), "+r"(c[1]), "+r"(c[2]), "+r"(c[3])
        : "r"(a[0]), "r"(a[1]), "r"(a[2]), "r"(a[3]), "r"(b0), "r"(b1));
}

__device__ __forceinline__ void cp_async16(void* dst, const void* src) {
    const uint32_t d = (uint32_t)__cvta_generic_to_shared(dst);
    asm volatile("cp.async.cg.shared.global [%0], [%1], 16;\n" :: "r"(d), "l"(src) : "memory");
}
__device__ __forceinline__ void cp_commit() {
    asm volatile("cp.async.commit_group;\n" ::: "memory");
}
template <int N> __device__ __forceinline__ void cp_wait() {
    asm volatile("cp.async.wait_group %0;\n" :: "n"(N) : "memory");
}

// 16KB ring chunk c (global counter): slot = c % 3, source period 10:
//   c10 in {0,1}  -> L3 k-halves at 10240 + c10*16384  (256 cols x k64)
//   c10 in {2..9} -> L4 [half][k64] at 43008 + (c10-2)*16384
// (consecutive k32 chunks of the R15 packing are contiguous, so pairing them
//  into k64 chunks needs no repacking). 2 cp.async16 per thread.
__device__ __forceinline__ void stage_chunk(int c, char* ring, int tid) {
    char* dst = ring + (c % NSLOT) * SLOT_BYTES;
    const int c10 = c % 10;
    const char* src = (const char*)g_Wpk +
        ((c10 < 2) ? 10240 + c10 * 16384 : 43008 + (c10 - 2) * 16384);
    cp_async16(dst + tid * 16,        src + tid * 16);
    cp_async16(dst + 8192 + tid * 16, src + 8192 + tid * 16);
    cp_commit();
}

// SMEM offsets (bytes). Activation strides 48/80/144/272: conflict-free ldmatrix.
#define SO_XS     0         //  3072
#define SO_H1     3072      //  5120
#define SO_H2     8192      //  9216
#define SO_H3     17408     // 17408
#define SO_XSTAGE 34816     //  4864  (fp32 x tile [19][64])
#define SO_STATIC 39680     // 10240  (L1+L2 weights, resident)
#define SO_RING   49920     // 49152  (3 x 16KB)
#define SO_BIAS   99072     //  3840
#define SO_W5     102912    //  2048
#define SO_SW     104960    //  3840
#define SO_DS0    108800    //   256
#define SO_DS1    109056    //   256
#define SO_QS     109312    //   256
#define SO_RMAX4  109568    //  1024  (float rmax[64][4]; reused as double red[64])
#define SO_ZS     110592    //   256
#define SMEM_BYTES 110848

// One GEMM pass, M=64: warp wm owns m16 rows [wm*16,+16), wn owns NW cols.
// RING=true: 3-slot 16KB ring; each outer iteration consumes one k64 chunk
// (two k32 sub-steps). RING=false: weights from static SMEM, barrier-free.
template <int KP, int NW, int SS, int DS, bool FUSE, bool RING>
__device__ __forceinline__ void run_pass(
    const int8_t* sA, int8_t* sD, char* ring, const char* wst, int wstride,
    const float* __restrict__ bias, const float* __restrict__ swc,
    const float* saIn, float* dsOut, float* sqs, float* rmax4,
    const float* w5, float* zacc,
    int ncol0, int chunk_col0, int& chunk, int wm, int wn, int lane, int tid)
{
    constexpr int N8 = NW / 8;
    const int g = lane >> 2, tq = lane & 3;

    int acc[N8][4];
#pragma unroll
    for (int n = 0; n < N8; ++n)
#pragma unroll
        for (int q = 0; q < 4; ++q) acc[n][q] = 0;

    const uint32_t abase = (uint32_t)__cvta_generic_to_shared(
        sA + (wm * 16 + (lane & 15)) * SS) + ((lane >> 4) << 4);
    const int wbyte = (((ncol0 - chunk_col0) * 4 + tq) << 3);   // base byte in slot

    if (RING) {
#pragma unroll 1
        for (int oc = 0; oc < KP / 64; ++oc) {
            cp_wait<1>();
            __syncthreads();                   // chunk-1 reads done in all warps
            stage_chunk(chunk + 2, ring, tid); // overwrites slot (chunk-1)%3
            const char* slotb = ring + (chunk % NSLOT) * SLOT_BYTES;
#pragma unroll
            for (int inner = 0; inner < 2; ++inner) {
                const char* slot = slotb + inner * 8192;
                const int cc = oc * 2 + inner;
                uint32_t a[4];
                asm volatile("ldmatrix.sync.aligned.m8n8.x4.shared.b16 {%0,%1,%2,%3},[%4];\n"
                    : "=r"(a[0]), "=r"(a[1]), "=r"(a[2]), "=r"(a[3])
                    : "r"(abase + cc * 32));
#pragma unroll
                for (int n8 = 0; n8 < N8; ++n8) {
                    const uint2 wv = *(const uint2*)(slot + wbyte + ((n8 * 8 + g) << 5));
                    imma(acc[n8], a, wv.x, wv.y);
                }
            }
            ++chunk;
        }
    } else {
#pragma unroll
        for (int cc = 0; cc < KP / 32; ++cc) {
            const char* slot = wst + cc * wstride;
            uint32_t a[4];
            asm volatile("ldmatrix.sync.aligned.m8n8.x4.shared.b16 {%0,%1,%2,%3},[%4];\n"
                : "=r"(a[0]), "=r"(a[1]), "=r"(a[2]), "=r"(a[3])
                : "r"(abase + cc * 32));
#pragma unroll
            for (int n8 = 0; n8 < N8; ++n8) {
                const uint2 wv = *(const uint2*)(slot + wbyte + ((n8 * 8 + g) << 5));
                imma(acc[n8], a, wv.x, wv.y);
            }
        }
    }

    // ---- epilogue: rows r0 (acc[.][0..1]) and r0+8 (acc[.][2..3]) ----
    const int r0 = wm * 16 + g;
    const float sa0 = saIn[r0], sa1 = saIn[r0 + 8];
    float lm0 = 0.f, lm1 = 0.f;

#pragma unroll
    for (int n8 = 0; n8 < N8; ++n8) {
        const int c0 = ncol0 + n8 * 8 + tq * 2;
        const float sw0 = swc[c0], sw1 = swc[c0 + 1];
        const float bb0 = bias[c0], bb1 = bias[c0 + 1];
        const float v0 = leaky(fmaf((float)acc[n8][0], sa0 * sw0, bb0));
        const float v1 = leaky(fmaf((float)acc[n8][1], sa0 * sw1, bb1));
        const float v2 = leaky(fmaf((float)acc[n8][2], sa1 * sw0, bb0));
        const float v3 = leaky(fmaf((float)acc[n8][3], sa1 * sw1, bb1));
        if (FUSE) {
            const float w50 = w5[c0], w51 = w5[c0 + 1];
            zacc[0] += v0 * w50 + v1 * w51;
            zacc[1] += v2 * w50 + v3 * w51;
        } else {
            lm0 = fmaxf(lm0, fmaxf(fabsf(v0), fabsf(v1)));
            lm1 = fmaxf(lm1, fmaxf(fabsf(v2), fabsf(v3)));
            acc[n8][0] = __float_as_int(v0); acc[n8][1] = __float_as_int(v1);
            acc[n8][2] = __float_as_int(v2); acc[n8][3] = __float_as_int(v3);
        }
    }

    if (!FUSE) {
        lm0 = fmaxf(lm0, __shfl_xor_sync(0xffffffffu, lm0, 1));
        lm0 = fmaxf(lm0, __shfl_xor_sync(0xffffffffu, lm0, 2));
        lm1 = fmaxf(lm1, __shfl_xor_sync(0xffffffffu, lm1, 1));
        lm1 = fmaxf(lm1, __shfl_xor_sync(0xffffffffu, lm1, 2));
        if (tq == 0) {
            rmax4[r0 * 4 + wn]       = lm0;
            rmax4[(r0 + 8) * 4 + wn] = lm1;
        }
        __syncthreads();
        if (tid < 64) {
            const float m = fmaxf(fmaxf(rmax4[tid * 4 + 0], rmax4[tid * 4 + 1]),
                                  fmaxf(rmax4[tid * 4 + 2], rmax4[tid * 4 + 3]));
            sqs[tid]   = (m > 0.f) ? 127.f / m : 0.f;
            dsOut[tid] = m * (1.f / 127.f);
        }
        __syncthreads();
        const float q0s = sqs[r0], q1s = sqs[r0 + 8];
#pragma unroll
        for (int n8 = 0; n8 < N8; ++n8) {
            const int c0 = ncol0 + n8 * 8 + tq * 2;
            const int i0 = (int)rintf(__int_as_float(acc[n8][0]) * q0s);
            const int i1 = (int)rintf(__int_as_float(acc[n8][1]) * q0s);
            const int i2 = (int)rintf(__int_as_float(acc[n8][2]) * q1s);
            const int i3 = (int)rintf(__int_as_float(acc[n8][3]) * q1s);
            *(uint16_t*)(sD + r0 * DS + c0) =
                (uint16_t)((i0 & 0xFF) | ((i1 & 0xFF) << 8));
            *(uint16_t*)(sD + (r0 + 8) * DS + c0) =
                (uint16_t)((i2 & 0xFF) | ((i3 & 0xFF) << 8));
        }
        __syncthreads();                       // sD visible to the next pass
    }
}

__global__ void __launch_bounds__(512, 2)
disc_kernel(const float* __restrict__ x, const float* __restrict__ lbl,
            const float* __restrict__ b1, const float* __restrict__ b2,
            const float* __restrict__ b3, const float* __restrict__ b4,
            const float* __restrict__ W5, const float* __restrict__ b5)
{
    extern __shared__ char sm[];
    int8_t* xs = (int8_t*)(sm + SO_XS);
    int8_t* h1 = (int8_t*)(sm + SO_H1);
    int8_t* h2 = (int8_t*)(sm + SO_H2);
    int8_t* h3 = (int8_t*)(sm + SO_H3);
    float* xstage = (float*)(sm + SO_XSTAGE);  // [19][64] fp32
    char*  wstatic = sm + SO_STATIC;
    char*  ring = sm + SO_RING;
    float* sbias = (float*)(sm + SO_BIAS);
    float* sw5   = (float*)(sm + SO_W5);
    float* ssw   = (float*)(sm + SO_SW);
    float* ds0   = (float*)(sm + SO_DS0);
    float* ds1   = (float*)(sm + SO_DS1);
    float* sqs   = (float*)(sm + SO_QS);
    float* rmax4 = (float*)(sm + SO_RMAX4);
    float* zs  = (float*)(sm + SO_ZS);

    const int tid = threadIdx.x, wid = tid >> 5, lane = tid & 31;
    const int wm = wid >> 2, wn = wid & 3;

    // ---- once-per-CTA prologue ----
    for (int off = tid * 16; off < 10240; off += 512 * 16)      // static L1/L2 w
        cp_async16(wstatic + off, (const char*)g_Wpk + off);
    cp_commit();
    stage_chunk(0, ring, tid);                                   // ring spin-up
    stage_chunk(1, ring, tid);

    for (int i = tid; i < 960; i += 512) {
        sbias[i] = (i < 64) ? b1[i] : (i < 192) ? b2[i - 64]
                 : (i < 448) ? b3[i - 192] : b4[i - 448];
        ssw[i] = g_sw[i];
    }
    sw5[tid] = W5[tid];
    const float b5v = b5[0];

    // x prefetch for first tile: one uint4 per thread (tid<304 = 19ch x 16seg).
    const int xc = tid >> 4, xseg = tid & 15;
    uint4 xreg = make_uint4(0, 0, 0, 0);
    {
        const int P0 = blockIdx.x * 64;
        if (tid < 304)
            xreg = *(const uint4*)((const char*)
                (x + (size_t)((P0 / HW_) * 19 + xc) * HW_ + (P0 % HW_)) + xseg * 16);
    }
    cp_wait<2>();                               // wstatic group done
    __syncthreads();

    double bce_acc = 0.0;
    int chunk = 0;

    for (int tile = blockIdx.x; tile < NT; tile += GRIDP) {
        const int P0 = tile * 64;

        // Spill x regs to SMEM; zero zs; load this tile's labels (in flight).
        if (tid < 304) *(uint4*)((char*)xstage + tid * 16) = xreg;
        float lblv = 0.f;
        if (tid < 64) { zs[tid] = 0.f; lblv = lbl[P0 + tid]; }
        __syncthreads();

        // Quantize x: 8 threads/pixel, per-pixel dynamic scale.
        {
            const int p = tid >> 3, q8 = tid & 7;
            float xv[3]; float m = 0.f;
#pragma unroll
            for (int j = 0; j < 3; ++j) {
                const int c = q8 * 3 + j;
                xv[j] = (c < 19) ? xstage[c * 64 + p] : 0.f;
                m = fmaxf(m, fabsf(xv[j]));
            }
            m = fmaxf(m, __shfl_xor_sync(0xffffffffu, m, 1));
            m = fmaxf(m, __shfl_xor_sync(0xffffffffu, m, 2));
            m = fmaxf(m, __shfl_xor_sync(0xffffffffu, m, 4));
            const float qsx = (m > 0.f) ? 127.f / m : 0.f;
            if (q8 == 0) ds0[p] = m * (1.f / 127.f);
#pragma unroll
            for (int j = 0; j < 3; ++j) {
                const int c = q8 * 3 + j;
                if (c < 19) xs[p * 48 + c] = (int8_t)(int)rintf(xv[j] * qsx);
            }
            for (int i = tid; i < 64 * 13; i += 512) {
                const int pp = i / 13, cc = 19 + i % 13;
                xs[pp * 48 + cc] = 0;
            }
        }

        // Prefetch next tile's x into registers (hidden under this tile).
        {
            const int tn = tile + GRIDP;
            if (tid < 304 && tn < NT) {
                const int Pn = tn * 64;
                xreg = *(const uint4*)((const char*)
                    (x + (size_t)((Pn / HW_) * 19 + xc) * HW_ + (Pn % HW_)) + xseg * 16);
            }
        }
        __syncthreads();                        // xs + ds0 visible

        run_pass<32,  16, 48,  80,  false, false>(xs, h1, ring, wstatic,        0,
            sbias,       ssw,       ds0, ds1, sqs, rmax4, nullptr, nullptr,
            wn * 16, 0, chunk, wm, wn, lane, tid);
        run_pass<64,  32, 80,  144, false, false>(h1, h2, ring, wstatic + 2048, 4096,
            sbias + 64,  ssw + 64,  ds1, ds0, sqs, rmax4, nullptr, nullptr,
            wn * 32, 0, chunk, wm, wn, lane, tid);
        run_pass<128, 64, 144, 272, false, true>(h2, h3, ring, nullptr, 0,
            sbias + 192, ssw + 192, ds0, ds1, sqs, rmax4, nullptr, nullptr,
            wn * 64, 0, chunk, wm, wn, lane, tid);

        float zacc[2] = {0.f, 0.f};
        run_pass<256, 64, 272, 1, true, true>(h3, nullptr, ring, nullptr, 0,
            sbias + 448, ssw + 448, ds1, nullptr, nullptr, nullptr, sw5, zacc,
            wn * 64, 0, chunk, wm, wn, lane, tid);
        run_pass<256, 64, 272, 1, true, true>(h3, nullptr, ring, nullptr, 0,
            sbias + 448, ssw + 448, ds1, nullptr, nullptr, nullptr, sw5, zacc,
            256 + wn * 64, 256, chunk, wm, wn, lane, tid);

        zacc[0] += __shfl_xor_sync(0xffffffffu, zacc[0], 1);
        zacc[0] += __shfl_xor_sync(0xffffffffu, zacc[0], 2);
        zacc[1] += __shfl_xor_sync(0xffffffffu, zacc[1], 1);
        zacc[1] += __shfl_xor_sync(0xffffffffu, zacc[1], 2);
        if ((lane & 3) == 0) {
            const int r0 = wm * 16 + (lane >> 2);
            atomicAdd(&zs[r0],     zacc[0]);
            atomicAdd(&zs[r0 + 8], zacc[1]);
        }
        __syncthreads();

        if (tid < 64) {
            const float z = zs[tid] + b5v;
            bce_acc += (double)(fmaxf(z, 0.f) - z * lblv + log1pf(expf(-fabsf(z))));
        }
        __syncthreads();                        // zs reads done before re-zero
    }

    // ---- final reduction: one atomicAdd per CTA ----
    cp_wait<0>();                               // drain dangling ring groups
    __syncthreads();
    double* dred = (double*)(sm + SO_RMAX4);    // 64 doubles = 512B, reuse
    if (tid < 64) dred[tid] = bce_acc;
    __syncthreads();
    if (tid == 0) {
        double s = 0.0;
        for (int i = 0; i < 64; ++i) s += dred[i];
        atomicAdd(&g_acc, s);
    }
}

__global__ void fin_kernel(float* out) {
    out[0] = (float)(g_acc * (1.0 / (double)NPIX));
}

extern "C" void kernel_launch(void* const* d_in, const int* in_sizes, int n_in,
                              void* d_out, int out_size) {
    (void)in_sizes; (void)n_in; (void)out_size;
    const float* x   = (const float*)d_in[0];
    const float* lbl = (const float*)d_in[1];
    const float* W1  = (const float*)d_in[2];
    const float* b1  = (const float*)d_in[3];
    const float* W2  = (const float*)d_in[4];
    const float* b2  = (const float*)d_in[5];
    const float* W3  = (const float*)d_in[6];
    const float* b3  = (const float*)d_in[7];
    const float* W4  = (const float*)d_in[8];
    const float* b4  = (const float*)d_in[9];
    const float* W5  = (const float*)d_in[10];
    const float* b5  = (const float*)d_in[11];

    cudaFuncSetAttribute(disc_kernel, cudaFuncAttributeMaxDynamicSharedMemorySize, SMEM_BYTES);

    prep_kernel<<<120, 256>>>(W1, W2, W3, W4);
    disc_kernel<<<GRIDP, 512, SMEM_BYTES>>>(x, lbl, b1, b2, b3, b4, W5, b5);
    fin_kernel<<<1, 1>>>((float*)d_out);
}